// round 5
// baseline (speedup 1.0000x reference)
#include <cuda_runtime.h>
#include <cuda_bf16.h>

// Problem constants (fixed by the reference)
#define BATCH   2
#define NPTS    8192
#define DIM     32
#define R2      0.0009f     // 0.03^2
#define SIMT    0.7f
#define EPSN    1e-8f
#define MINLEAF 10

#define GRIDC   14                      // ceil(0.4 / 0.03)
#define NCELL   (GRIDC * GRIDC * GRIDC) // 2744
#define CAP     32                      // bucket capacity (mean occupancy ~1.5)
#define INVC    33.333332f              // 1 / 0.03
#define MARGIN  0.0302f                 // radius + safety margin for cell-range bound

#define QTPB    256                     // query threads per block
#define WPB     (QTPB / 32)             // 8 warps (points) per block
#define FULL    0xffffffffu

// Scratch (static __device__ — no allocations allowed)
__device__ float  g_en[BATCH * NPTS * DIM];          // normalized embeddings (2 MB)
__device__ int    g_cellcnt[BATCH * NCELL];          // points per cell
__device__ float4 g_bucket[BATCH * NCELL * CAP];     // (x,y,z, bitcast local idx)
__device__ int    g_leafcnt[BATCH];

__global__ void zero_kernel() {
    int t = blockIdx.x * blockDim.x + threadIdx.x;
    if (t < BATCH * NCELL) g_cellcnt[t] = 0;
    if (t < BATCH)         g_leafcnt[t] = 0;
}

__global__ void prep_kernel(const float* __restrict__ points,
                            const float* __restrict__ emb,
                            const int*   __restrict__ leaf) {
    int idx = blockIdx.x * blockDim.x + threadIdx.x;
    if (idx >= BATCH * NPTS) return;
    int b = idx / NPTS;
    int j = idx - b * NPTS;

    // normalized embedding with clamped norm (matches reference eps semantics)
    const float4* e4 = (const float4*)(emb + (size_t)idx * DIM);
    float v[DIM];
    float s = 0.f;
#pragma unroll
    for (int q = 0; q < DIM / 4; q++) {
        float4 t = __ldg(e4 + q);
        v[4*q+0] = t.x; v[4*q+1] = t.y; v[4*q+2] = t.z; v[4*q+3] = t.w;
        s = fmaf(t.x, t.x, s); s = fmaf(t.y, t.y, s);
        s = fmaf(t.z, t.z, s); s = fmaf(t.w, t.w, s);
    }
    float inv = 1.f / fmaxf(sqrtf(s), EPSN);
    float4* o4 = (float4*)(g_en + (size_t)idx * DIM);
#pragma unroll
    for (int q = 0; q < DIM / 4; q++)
        o4[q] = make_float4(v[4*q] * inv, v[4*q+1] * inv, v[4*q+2] * inv, v[4*q+3] * inv);

    // leaf count + grid insert (only leaf points can be neighbors)
    int lf = leaf[idx] > 0;
    unsigned msk = __ballot_sync(FULL, lf);
    if ((threadIdx.x & 31) == 0 && msk)
        atomicAdd(&g_leafcnt[b], __popc(msk));

    if (lf) {
        float x = points[3 * (size_t)idx];
        float y = points[3 * (size_t)idx + 1];
        float z = points[3 * (size_t)idx + 2];
        int cx = min(GRIDC - 1, (int)(x * INVC));
        int cy = min(GRIDC - 1, (int)(y * INVC));
        int cz = min(GRIDC - 1, (int)(z * INVC));
        int c = b * NCELL + (cz * GRIDC + cy) * GRIDC + cx;
        int pos = atomicAdd(&g_cellcnt[c], 1);
        if (pos < CAP)
            g_bucket[(size_t)c * CAP + pos] = make_float4(x, y, z, __int_as_float(j));
    }
}

// One WARP per query point. Lane-parallel candidate testing, lane-sliced
// accumulator (lane k owns embedding component k), lane-parallel MLP.
__global__ void __launch_bounds__(QTPB)
query_kernel(const float* __restrict__ points,
             const float* __restrict__ emb,
             const int*   __restrict__ leaf,
             const float* __restrict__ W1,
             const float* __restrict__ b1,
             const float* __restrict__ W2,
             const float* __restrict__ b2,
             float* __restrict__ out) {
    __shared__ float sW1[2 * DIM * DIM];
    __shared__ float sW2[DIM * DIM];
    __shared__ float sb1[DIM];
    __shared__ float sb2[DIM];

    for (int t = threadIdx.x; t < 2 * DIM * DIM; t += QTPB) sW1[t] = W1[t];
    for (int t = threadIdx.x; t < DIM * DIM; t += QTPB)     sW2[t] = W2[t];
    if (threadIdx.x < DIM) { sb1[threadIdx.x] = b1[threadIdx.x]; sb2[threadIdx.x] = b2[threadIdx.x]; }
    __syncthreads();

    const int lane = threadIdx.x & 31;
    const int w    = blockIdx.x * WPB + (threadIdx.x >> 5);   // global point id
    const int b    = w / NPTS;
    const size_t gi = (size_t)w;                               // == b*NPTS + i

    // own raw point (warp-uniform broadcast loads)
    const float xi = __ldg(points + 3 * gi);
    const float yi = __ldg(points + 3 * gi + 1);
    const float zi = __ldg(points + 3 * gi + 2);

    // own raw embedding, lane-sliced (one coalesced 128B warp load)
    const float ei_l = __ldg(emb + gi * DIM + lane);

    // own normalized embedding, FULL vector per lane (warp-uniform; for sim dots)
    float eni[DIM];
    {
        const float4* e4 = (const float4*)(g_en + gi * DIM);
#pragma unroll
        for (int q = 0; q < 8; q++) {
            float4 t = __ldg(e4 + q);
            eni[4*q] = t.x; eni[4*q+1] = t.y; eni[4*q+2] = t.z; eni[4*q+3] = t.w;
        }
    }

    // cell range covering the open ball (margin >> fp rounding)
    const int cx0 = max(0, (int)((xi - MARGIN) * INVC)), cx1 = min(GRIDC - 1, (int)((xi + MARGIN) * INVC));
    const int cy0 = max(0, (int)((yi - MARGIN) * INVC)), cy1 = min(GRIDC - 1, (int)((yi + MARGIN) * INVC));
    const int cz0 = max(0, (int)((zi - MARGIN) * INVC)), cz1 = min(GRIDC - 1, (int)((zi + MARGIN) * INVC));
    const int nx = cx1 - cx0 + 1, ny = cy1 - cy0 + 1, nz = cz1 - cz0 + 1;
    const int nxy = nx * ny, nc = nxy * nz;   // <= 64

    // prefetch all covered cell counts in parallel (up to 64 -> 2 regs per lane)
    int mycell0 = 0, mycnt0 = 0, mycell1 = 0, mycnt1 = 0;
    {
        int id = lane;
        if (id < nc) {
            int cz = id / nxy, r = id - cz * nxy, cy = r / nx, cx = r - cy * nx;
            mycell0 = ((cz0 + cz) * GRIDC + (cy0 + cy)) * GRIDC + (cx0 + cx);
            mycnt0  = __ldg(g_cellcnt + b * NCELL + mycell0);
        }
        id = lane + 32;
        if (id < nc) {
            int cz = id / nxy, r = id - cz * nxy, cy = r / nx, cx = r - cy * nx;
            mycell1 = ((cz0 + cz) * GRIDC + (cy0 + cy)) * GRIDC + (cx0 + cx);
            mycnt1  = __ldg(g_cellcnt + b * NCELL + mycell1);
        }
    }

    int nbcnt = 0, cnt = 0;
    float acc_l = 0.f;                                  // lane-sliced accumulator
    const float* enb  = g_en + (size_t)b * NPTS * DIM;
    const float* embb = emb  + (size_t)b * NPTS * DIM;

    for (int cc = 0; cc < nc; cc++) {                   // warp-uniform loop
        int n    = (cc < 32) ? __shfl_sync(FULL, mycnt0, cc) : __shfl_sync(FULL, mycnt1, cc - 32);
        if (n == 0) continue;
        int cell = (cc < 32) ? __shfl_sync(FULL, mycell0, cc) : __shfl_sync(FULL, mycell1, cc - 32);
        n = min(n, CAP);

        // all lanes test one slot each (bucket is CAP-padded: load always in-bounds)
        float4 p = __ldg(g_bucket + ((size_t)b * NCELL + cell) * CAP + lane);
        int    j = __float_as_int(p.w);
        float dx = xi - p.x, dy = yi - p.y, dz = zi - p.z;
        float d2 = fmaf(dx, dx, fmaf(dy, dy, dz * dz));
        bool pass = (lane < n) && (d2 < R2);
        unsigned m = __ballot_sync(FULL, pass);
        nbcnt += __popc(m);
        if (m) {
            // sim dot per passing lane (independent 8x LDG.128 + 32 FMA)
            float dot = -2.f;
            if (pass) {
                const float4* ej = (const float4*)(enb + (size_t)j * DIM);
                dot = 0.f;
#pragma unroll
                for (int q = 0; q < 8; q++) {
                    float4 v = __ldg(ej + q);
                    dot = fmaf(v.x, eni[4*q],   dot);
                    dot = fmaf(v.y, eni[4*q+1], dot);
                    dot = fmaf(v.z, eni[4*q+2], dot);
                    dot = fmaf(v.w, eni[4*q+3], dot);
                }
            }
            unsigned ms = __ballot_sync(FULL, dot > SIMT);
            cnt += __popc(ms);
            while (ms) {                                // rare: ~1 iter per point
                int l = __ffs(ms) - 1; ms &= ms - 1;
                int jj = __shfl_sync(FULL, j, l);
                acc_l += __ldg(embb + (size_t)jj * DIM + lane);  // RAW embedding (exact)
            }
        }
    }

    // ---- lane-parallel MLP: lane o owns output o ----
    const float rinv  = 1.f / (float)(cnt > 0 ? cnt : 1);
    const float c_acc = acc_l * rinv;                   // lane-sliced mean_sim

    float h = sb1[lane];
#pragma unroll
    for (int k = 0; k < DIM; k++) {
        float c = __shfl_sync(FULL, ei_l, k);
        h = fmaf(c, sW1[k * DIM + lane], h);
    }
#pragma unroll
    for (int k = 0; k < DIM; k++) {
        float c = __shfl_sync(FULL, c_acc, k);
        h = fmaf(c, sW1[(DIM + k) * DIM + lane], h);
    }
    h = fmaxf(h, 0.f);

    float ov = sb2[lane];
#pragma unroll
    for (int k = 0; k < DIM; k++) {
        float c = __shfl_sync(FULL, h, k);
        ov = fmaf(c, sW2[k * DIM + lane], ov);
    }

    bool cond = (__ldg(leaf + gi) > 0) && (nbcnt > 1) && (cnt > 0)
             && (__ldg(&g_leafcnt[b]) >= MINLEAF);

    out[gi * DIM + lane] = cond ? ov : ei_l;            // coalesced 128B per warp
}

extern "C" void kernel_launch(void* const* d_in, const int* in_sizes, int n_in,
                              void* d_out, int out_size) {
    const float* points = (const float*)d_in[0];
    const float* emb    = (const float*)d_in[1];
    const int*   leaf   = (const int*)d_in[2];
    const float* W1     = (const float*)d_in[3];
    const float* b1     = (const float*)d_in[4];
    const float* W2     = (const float*)d_in[5];
    const float* b2     = (const float*)d_in[6];
    float* out = (float*)d_out;

    zero_kernel<<<(BATCH * NCELL + 255) / 256, 256>>>();
    prep_kernel<<<(BATCH * NPTS + 127) / 128, 128>>>(points, emb, leaf);
    query_kernel<<<BATCH * NPTS / WPB, QTPB>>>(points, emb, leaf, W1, b1, W2, b2, out);
}

// round 6
// speedup vs baseline: 1.9103x; 1.9103x over previous
#include <cuda_runtime.h>
#include <cuda_bf16.h>

// Problem constants (fixed by the reference)
#define BATCH   2
#define NPTS    8192
#define DIM     32
#define R2      0.0009f     // 0.03^2
#define SIMT    0.7f
#define EPSN    1e-8f
#define MINLEAF 10

#define GRIDC   14                      // ceil(0.4 / 0.03)
#define NCELL   (GRIDC * GRIDC * GRIDC) // 2744
#define CAP     32                      // bucket capacity (mean occupancy ~1.5)
#define INVC    33.333332f              // 1 / 0.03
#define MARGIN  0.0302f                 // radius + safety margin for cell-range bound

#define QTPB    256                     // query threads per block
#define LPP     8                       // lanes per point
#define PPB     (QTPB / LPP)            // 32 points per block
#define FULL    0xffffffffu
#define PAD     33                      // smem row pad (bank-conflict-free)

// Scratch (static __device__ — no allocations allowed)
__device__ float  g_en[BATCH * NPTS * DIM];          // normalized embeddings (2 MB)
__device__ int    g_cellcnt[BATCH * NCELL];          // points per cell
__device__ float4 g_bucket[BATCH * NCELL * CAP];     // (x,y,z, bitcast local idx)
__device__ int    g_leafcnt[BATCH];

__global__ void zero_kernel() {
    int t = blockIdx.x * blockDim.x + threadIdx.x;
    if (t < BATCH * NCELL) g_cellcnt[t] = 0;
    if (t < BATCH)         g_leafcnt[t] = 0;
}

__global__ void prep_kernel(const float* __restrict__ points,
                            const float* __restrict__ emb,
                            const int*   __restrict__ leaf) {
    int idx = blockIdx.x * blockDim.x + threadIdx.x;
    if (idx >= BATCH * NPTS) return;
    int b = idx / NPTS;
    int j = idx - b * NPTS;

    // normalized embedding with clamped norm (matches reference eps semantics)
    const float4* e4 = (const float4*)(emb + (size_t)idx * DIM);
    float v[DIM];
    float s = 0.f;
#pragma unroll
    for (int q = 0; q < DIM / 4; q++) {
        float4 t = __ldg(e4 + q);
        v[4*q+0] = t.x; v[4*q+1] = t.y; v[4*q+2] = t.z; v[4*q+3] = t.w;
        s = fmaf(t.x, t.x, s); s = fmaf(t.y, t.y, s);
        s = fmaf(t.z, t.z, s); s = fmaf(t.w, t.w, s);
    }
    float inv = 1.f / fmaxf(sqrtf(s), EPSN);
    float4* o4 = (float4*)(g_en + (size_t)idx * DIM);
#pragma unroll
    for (int q = 0; q < DIM / 4; q++)
        o4[q] = make_float4(v[4*q] * inv, v[4*q+1] * inv, v[4*q+2] * inv, v[4*q+3] * inv);

    // leaf count + grid insert (only leaf points can be neighbors)
    int lf = leaf[idx] > 0;
    unsigned msk = __ballot_sync(FULL, lf);
    if ((threadIdx.x & 31) == 0 && msk)
        atomicAdd(&g_leafcnt[b], __popc(msk));

    if (lf) {
        float x = points[3 * (size_t)idx];
        float y = points[3 * (size_t)idx + 1];
        float z = points[3 * (size_t)idx + 2];
        int cx = min(GRIDC - 1, (int)(x * INVC));
        int cy = min(GRIDC - 1, (int)(y * INVC));
        int cz = min(GRIDC - 1, (int)(z * INVC));
        int c = b * NCELL + (cz * GRIDC + cy) * GRIDC + cx;
        int pos = atomicAdd(&g_cellcnt[c], 1);
        if (pos < CAP)
            g_bucket[(size_t)c * CAP + pos] = make_float4(x, y, z, __int_as_float(j));
    }
}

// 8 lanes per point; lane-per-cell with uniform control flow; no warp
// collectives in the scan loop; one shfl reduce per point at the end.
__global__ void __launch_bounds__(QTPB)
query_kernel(const float* __restrict__ points,
             const float* __restrict__ emb,
             const int*   __restrict__ leaf,
             const float* __restrict__ W1,
             const float* __restrict__ b1,
             const float* __restrict__ W2,
             const float* __restrict__ b2,
             float* __restrict__ out) {
    __shared__ __align__(16) float sW1[2 * DIM * DIM];
    __shared__ __align__(16) float sW2[DIM * DIM];
    __shared__ float sb1[DIM];
    __shared__ float sb2[DIM];
    __shared__ int   s_cnt[NCELL];               // per-batch cell counts (11 KB)
    __shared__ float s_ei[PPB * PAD];            // raw embeddings of block's points
    __shared__ float s_acc[PPB * PAD];           // sim-sum accumulators (atomicAdd)
    __shared__ float s_h[PPB * PAD];             // hidden layer broadcast

    const int tid   = threadIdx.x;
    const int pt    = tid / LPP;                 // 0..31  local point
    const int lane8 = tid % LPP;                 // 0..7   lane within point group
    const int gi    = blockIdx.x * PPB + pt;     // global point id
    const int b     = gi / NPTS;

    // stage: weights, biases, cell counts, raw embeddings; zero accumulators
    for (int t = tid; t < 2 * DIM * DIM; t += QTPB) sW1[t] = W1[t];
    for (int t = tid; t < DIM * DIM; t += QTPB)     sW2[t] = W2[t];
    if (tid < DIM) { sb1[tid] = b1[tid]; sb2[tid] = b2[tid]; }
    for (int t = tid; t < NCELL; t += QTPB)         s_cnt[t] = g_cellcnt[b * NCELL + t];
    for (int t = tid; t < PPB * DIM; t += QTPB) {
        int p = t / DIM, k = t - p * DIM;
        s_ei[p * PAD + k] = __ldg(emb + ((size_t)blockIdx.x * PPB + p) * DIM + k);
    }
    for (int t = tid; t < PPB * PAD; t += QTPB)     s_acc[t] = 0.f;
    __syncthreads();

    // own raw point (broadcast within group)
    const float xi = __ldg(points + 3 * (size_t)gi);
    const float yi = __ldg(points + 3 * (size_t)gi + 1);
    const float zi = __ldg(points + 3 * (size_t)gi + 2);

    // own normalized embedding (broadcast loads; each lane keeps full vector)
    float eni[DIM];
    {
        const float4* e4 = (const float4*)(g_en + (size_t)gi * DIM);
#pragma unroll
        for (int q = 0; q < 8; q++) {
            float4 t = __ldg(e4 + q);
            eni[4*q] = t.x; eni[4*q+1] = t.y; eni[4*q+2] = t.z; eni[4*q+3] = t.w;
        }
    }

    // covered cell range (margin >> fp rounding)
    const int cx0 = max(0, (int)((xi - MARGIN) * INVC)), cx1 = min(GRIDC - 1, (int)((xi + MARGIN) * INVC));
    const int cy0 = max(0, (int)((yi - MARGIN) * INVC)), cy1 = min(GRIDC - 1, (int)((yi + MARGIN) * INVC));
    const int cz0 = max(0, (int)((zi - MARGIN) * INVC)), cz1 = min(GRIDC - 1, (int)((zi + MARGIN) * INVC));
    const int nx = cx1 - cx0 + 1, ny = cy1 - cy0 + 1, nz = cz1 - cz0 + 1;
    const int nxy = nx * ny, nc = nxy * nz;      // <= 64

    int nbcnt = 0, cnt = 0;
    const float* enb  = g_en + (size_t)b * NPTS * DIM;
    const float* embb = emb  + (size_t)b * NPTS * DIM;
    float* accp = s_acc + pt * PAD;

#pragma unroll
    for (int s = 0; s < 64 / LPP; s++) {         // uniform flow; lane owns cc
        int cc = lane8 + s * LPP;
        if (cc < nc) {
            int cz = cc / nxy; int r = cc - cz * nxy;
            int cy = r / nx;   int cx = r - cy * nx;
            int cell = ((cz0 + cz) * GRIDC + (cy0 + cy)) * GRIDC + (cx0 + cx);
            int n = min(s_cnt[cell], CAP);
            const float4* bk = g_bucket + ((size_t)b * NCELL + cell) * CAP;
            for (int k = 0; k < n; k++) {
                float4 p = __ldg(bk + k);
                float dx = xi - p.x, dy = yi - p.y, dz = zi - p.z;
                float d2 = fmaf(dx, dx, fmaf(dy, dy, dz * dz));
                if (d2 < R2) {
                    nbcnt++;
                    int j = __float_as_int(p.w);
                    const float4* ej = (const float4*)(enb + (size_t)j * DIM);
                    float dot = 0.f;
#pragma unroll
                    for (int q = 0; q < 8; q++) {
                        float4 v = __ldg(ej + q);
                        dot = fmaf(v.x, eni[4*q],   dot);
                        dot = fmaf(v.y, eni[4*q+1], dot);
                        dot = fmaf(v.z, eni[4*q+2], dot);
                        dot = fmaf(v.w, eni[4*q+3], dot);
                    }
                    if (dot > SIMT) {            // rare: accumulate RAW embedding
                        cnt++;
                        const float4* rj = (const float4*)(embb + (size_t)j * DIM);
#pragma unroll
                        for (int q = 0; q < 8; q++) {
                            float4 v = __ldg(rj + q);
                            atomicAdd(accp + 4*q,     v.x);
                            atomicAdd(accp + 4*q + 1, v.y);
                            atomicAdd(accp + 4*q + 2, v.z);
                            atomicAdd(accp + 4*q + 3, v.w);
                        }
                    }
                }
            }
        }
    }

    // group reduce (butterfly: all 8 lanes end with totals)
#pragma unroll
    for (int d = 1; d < LPP; d <<= 1) {
        nbcnt += __shfl_xor_sync(FULL, nbcnt, d);
        cnt   += __shfl_xor_sync(FULL, cnt, d);
    }
    __syncthreads();                             // s_acc complete for all points

    // ---- lane-parallel MLP: lane8 owns outputs [lane8*4, lane8*4+4) ----
    const float rinv = 1.f / (float)(cnt > 0 ? cnt : 1);
    const int   ob   = lane8 * 4;

    float h0 = sb1[ob], h1 = sb1[ob+1], h2 = sb1[ob+2], h3 = sb1[ob+3];
#pragma unroll 8
    for (int k = 0; k < DIM; k++) {
        float c = s_ei[pt * PAD + k];
        float4 wv = *(const float4*)(sW1 + k * DIM + ob);
        h0 = fmaf(c, wv.x, h0); h1 = fmaf(c, wv.y, h1);
        h2 = fmaf(c, wv.z, h2); h3 = fmaf(c, wv.w, h3);
    }
#pragma unroll 8
    for (int k = 0; k < DIM; k++) {
        float c = s_acc[pt * PAD + k] * rinv;
        float4 wv = *(const float4*)(sW1 + (DIM + k) * DIM + ob);
        h0 = fmaf(c, wv.x, h0); h1 = fmaf(c, wv.y, h1);
        h2 = fmaf(c, wv.z, h2); h3 = fmaf(c, wv.w, h3);
    }
    h0 = fmaxf(h0, 0.f); h1 = fmaxf(h1, 0.f); h2 = fmaxf(h2, 0.f); h3 = fmaxf(h3, 0.f);

    s_h[pt * PAD + ob]     = h0;
    s_h[pt * PAD + ob + 1] = h1;
    s_h[pt * PAD + ob + 2] = h2;
    s_h[pt * PAD + ob + 3] = h3;
    __syncthreads();

    float o0 = sb2[ob], o1 = sb2[ob+1], o2 = sb2[ob+2], o3 = sb2[ob+3];
#pragma unroll 8
    for (int k = 0; k < DIM; k++) {
        float c = s_h[pt * PAD + k];
        float4 wv = *(const float4*)(sW2 + k * DIM + ob);
        o0 = fmaf(c, wv.x, o0); o1 = fmaf(c, wv.y, o1);
        o2 = fmaf(c, wv.z, o2); o3 = fmaf(c, wv.w, o3);
    }

    bool cond = (__ldg(leaf + gi) > 0) && (nbcnt > 1) && (cnt > 0)
             && (__ldg(&g_leafcnt[b]) >= MINLEAF);

    float4 res;
    if (cond) res = make_float4(o0, o1, o2, o3);
    else      res = make_float4(s_ei[pt * PAD + ob],     s_ei[pt * PAD + ob + 1],
                                s_ei[pt * PAD + ob + 2], s_ei[pt * PAD + ob + 3]);
    *(float4*)(out + (size_t)gi * DIM + ob) = res;   // coalesced 128B per point
}

extern "C" void kernel_launch(void* const* d_in, const int* in_sizes, int n_in,
                              void* d_out, int out_size) {
    const float* points = (const float*)d_in[0];
    const float* emb    = (const float*)d_in[1];
    const int*   leaf   = (const int*)d_in[2];
    const float* W1     = (const float*)d_in[3];
    const float* b1     = (const float*)d_in[4];
    const float* W2     = (const float*)d_in[5];
    const float* b2     = (const float*)d_in[6];
    float* out = (float*)d_out;

    zero_kernel<<<(BATCH * NCELL + 255) / 256, 256>>>();
    prep_kernel<<<(BATCH * NPTS + 127) / 128, 128>>>(points, emb, leaf);
    query_kernel<<<BATCH * NPTS / PPB, QTPB>>>(points, emb, leaf, W1, b1, W2, b2, out);
}

// round 7
// speedup vs baseline: 2.0432x; 1.0695x over previous
#include <cuda_runtime.h>
#include <cuda_bf16.h>

// Problem constants (fixed by the reference)
#define BATCH   2
#define NPTS    8192
#define DIM     32
#define R2      0.0009f     // 0.03^2
#define SIMT    0.7f
#define EPSN    1e-8f
#define MINLEAF 10

#define GRIDC   14                      // ceil(0.4 / 0.03)
#define NCELL   (GRIDC * GRIDC * GRIDC) // 2744
#define CAP     32                      // bucket capacity (mean occupancy ~1.5)
#define INVC    33.333332f              // 1 / 0.03
#define MARGIN  0.0302f                 // radius + safety margin for cell-range bound

#define TPB     256
#define NB      592                     // 148 SMs x 4 blocks: provably co-resident
#define LPP     16                      // lanes per point
#define PPQ     (TPB / LPP)             // 16 points per tile
#define NTILE   (BATCH * NPTS / PPQ)    // 1024
#define FULL    0xffffffffu
#define PAD     36                      // smem row pad: 16B-aligned, conflict-safe

// Scratch (static __device__ — no allocations allowed)
__device__ float  g_en[BATCH * NPTS * DIM];          // normalized embeddings
__device__ int    g_cellcnt[BATCH * NCELL];
__device__ float4 g_bucket[BATCH * NCELL * CAP];     // (x,y,z, bitcast local idx)
__device__ int    g_leafcnt[BATCH];
__device__ int    g_bar_arrive;                      // zero-initialized
__device__ volatile int g_bar_gen;                   // monotonic epoch (never reset)

// Sense-reversal grid barrier. Safe because launch_bounds(TPB,4) + NB=148*4
// guarantees all NB blocks are resident in wave 1 (regs<=64, smem 32KB*4<=228KB).
__device__ __forceinline__ void grid_barrier() {
    __syncthreads();
    if (threadIdx.x == 0) {
        int gen = g_bar_gen;
        __threadfence();
        if (atomicAdd(&g_bar_arrive, 1) == NB - 1) {
            atomicExch(&g_bar_arrive, 0);
            __threadfence();
            g_bar_gen = gen + 1;                     // release
        } else {
            while (g_bar_gen == gen) { __nanosleep(20); }
        }
        __threadfence();
    }
    __syncthreads();
}

__global__ void __launch_bounds__(TPB, 4)
fused_kernel(const float* __restrict__ points,
             const float* __restrict__ emb,
             const int*   __restrict__ leaf,
             const float* __restrict__ W1,
             const float* __restrict__ b1,
             const float* __restrict__ W2,
             const float* __restrict__ b2,
             float* __restrict__ out) {
    __shared__ __align__(16) float sW1[2 * DIM * DIM];   // 8 KB
    __shared__ __align__(16) float sW2[DIM * DIM];       // 4 KB
    __shared__ float sb1[DIM];
    __shared__ float sb2[DIM];
    __shared__ int   s_cnt[NCELL];                       // 10.7 KB
    __shared__ __align__(16) float s_en[PPQ * PAD];      // normalized emb of tile points
    __shared__ __align__(16) float s_ei[PPQ * PAD];      // raw emb of tile points
    __shared__ float s_acc[PPQ * PAD];                   // sim-sum accumulators
    __shared__ float s_h[PPQ * PAD];                     // hidden layer

    const int tid = threadIdx.x;
    const int gtid = blockIdx.x * TPB + tid;

    // ---- Phase Z: zero grid state (151552 threads >> 5490 elements) ----
    if (gtid < BATCH * NCELL) g_cellcnt[gtid] = 0;
    if (gtid < BATCH)         g_leafcnt[gtid] = 0;
    grid_barrier();

    // ---- Phase P: prep (first 64 blocks; warps fully active or fully idle) ----
    if (gtid < BATCH * NPTS) {
        const int idx = gtid;
        const int b = idx / NPTS;
        const int j = idx - b * NPTS;

        const float4* e4 = (const float4*)(emb + (size_t)idx * DIM);
        float v[DIM];
        float s = 0.f;
#pragma unroll
        for (int q = 0; q < 8; q++) {
            float4 t = __ldg(e4 + q);
            v[4*q+0] = t.x; v[4*q+1] = t.y; v[4*q+2] = t.z; v[4*q+3] = t.w;
            s = fmaf(t.x, t.x, s); s = fmaf(t.y, t.y, s);
            s = fmaf(t.z, t.z, s); s = fmaf(t.w, t.w, s);
        }
        float inv = 1.f / fmaxf(sqrtf(s), EPSN);
        float4* o4 = (float4*)(g_en + (size_t)idx * DIM);
#pragma unroll
        for (int q = 0; q < 8; q++)
            o4[q] = make_float4(v[4*q] * inv, v[4*q+1] * inv, v[4*q+2] * inv, v[4*q+3] * inv);

        int lf = leaf[idx] > 0;
        unsigned msk = __ballot_sync(FULL, lf);
        if ((tid & 31) == 0 && msk)
            atomicAdd(&g_leafcnt[b], __popc(msk));

        if (lf) {
            float x = points[3 * (size_t)idx];
            float y = points[3 * (size_t)idx + 1];
            float z = points[3 * (size_t)idx + 2];
            int cx = min(GRIDC - 1, (int)(x * INVC));
            int cy = min(GRIDC - 1, (int)(y * INVC));
            int cz = min(GRIDC - 1, (int)(z * INVC));
            int c = b * NCELL + (cz * GRIDC + cy) * GRIDC + cx;
            int pos = atomicAdd(&g_cellcnt[c], 1);
            if (pos < CAP)
                g_bucket[(size_t)c * CAP + pos] = make_float4(x, y, z, __int_as_float(j));
        }
    }
    grid_barrier();

    // ---- Phase Q: query, 16 lanes per point, 16 points per tile ----
    for (int t = tid; t < 2 * DIM * DIM; t += TPB) sW1[t] = W1[t];
    for (int t = tid; t < DIM * DIM; t += TPB)     sW2[t] = W2[t];
    if (tid < DIM) { sb1[tid] = b1[tid]; sb2[tid] = b2[tid]; }

    const int pt = tid >> 4;            // 0..15  local point
    const int ln = tid & 15;            // 0..15  lane within point group
    int cur_b = -1;

    for (int tile = blockIdx.x; tile < NTILE; tile += NB) {
        const int gi0 = tile * PPQ;
        const int b = gi0 / NPTS;       // uniform within tile (PPQ | NPTS)

        if (b != cur_b) {
            __syncthreads();            // protect s_cnt readers of previous tile
            for (int t = tid; t < NCELL; t += TPB) s_cnt[t] = g_cellcnt[b * NCELL + t];
            cur_b = b;
        }
        // stage tile embeddings (raw + normalized), zero accumulators
        for (int t = tid; t < PPQ * DIM; t += TPB) {
            int p = t >> 5, k = t & 31;
            s_ei[p * PAD + k]  = __ldg(emb  + ((size_t)gi0 + p) * DIM + k);
            s_en[p * PAD + k]  = g_en[((size_t)gi0 + p) * DIM + k];
            s_acc[p * PAD + k] = 0.f;
        }
        __syncthreads();

        const int gi = gi0 + pt;
        const float xi = __ldg(points + 3 * (size_t)gi);
        const float yi = __ldg(points + 3 * (size_t)gi + 1);
        const float zi = __ldg(points + 3 * (size_t)gi + 2);

        const int cx0 = max(0, (int)((xi - MARGIN) * INVC)), cx1 = min(GRIDC - 1, (int)((xi + MARGIN) * INVC));
        const int cy0 = max(0, (int)((yi - MARGIN) * INVC)), cy1 = min(GRIDC - 1, (int)((yi + MARGIN) * INVC));
        const int cz0 = max(0, (int)((zi - MARGIN) * INVC)), cz1 = min(GRIDC - 1, (int)((zi + MARGIN) * INVC));
        const int nx = cx1 - cx0 + 1, ny = cy1 - cy0 + 1, nz = cz1 - cz0 + 1;
        const int nxy = nx * ny, nc = nxy * nz;          // <= 64
        const float invnxy = 1.f / (float)nxy;
        const float invnx  = 1.f / (float)nx;

        int nbcnt = 0, cnt = 0;
        const float* enb  = g_en + (size_t)b * NPTS * DIM;
        const float* embb = emb  + (size_t)b * NPTS * DIM;
        const float* en_i = s_en + pt * PAD;
        float* accp = s_acc + pt * PAD;

#pragma unroll
        for (int s = 0; s < 64 / LPP; s++) {             // 4 iters; lane owns cc
            int cc = ln + s * LPP;
            if (cc < nc) {
                // division-free decode: exact for cc<64 (0.5 offset >> fp error)
                int cz = (int)(((float)cc + 0.5f) * invnxy);
                int r  = cc - cz * nxy;
                int cy = (int)(((float)r + 0.5f) * invnx);
                int cx = r - cy * nx;
                int cell = ((cz0 + cz) * GRIDC + (cy0 + cy)) * GRIDC + (cx0 + cx);
                int n = min(s_cnt[cell], CAP);
                const float4* bk = g_bucket + ((size_t)b * NCELL + cell) * CAP;
                for (int k = 0; k < n; k++) {
                    float4 p = __ldg(bk + k);
                    float dx = xi - p.x, dy = yi - p.y, dz = zi - p.z;
                    float d2 = fmaf(dx, dx, fmaf(dy, dy, dz * dz));
                    if (d2 < R2) {
                        nbcnt++;
                        int j = __float_as_int(p.w);
                        const float4* ej = (const float4*)(enb + (size_t)j * DIM);
                        float dot = 0.f;
#pragma unroll
                        for (int q = 0; q < 8; q++) {
                            float4 v = __ldg(ej + q);
                            float4 u = *(const float4*)(en_i + 4 * q);  // broadcast LDS.128
                            dot = fmaf(v.x, u.x, dot); dot = fmaf(v.y, u.y, dot);
                            dot = fmaf(v.z, u.z, dot); dot = fmaf(v.w, u.w, dot);
                        }
                        if (dot > SIMT) {                // rare: accumulate RAW embedding
                            cnt++;
                            const float4* rj = (const float4*)(embb + (size_t)j * DIM);
#pragma unroll
                            for (int q = 0; q < 8; q++) {
                                float4 v = __ldg(rj + q);
                                atomicAdd(accp + 4*q,     v.x);
                                atomicAdd(accp + 4*q + 1, v.y);
                                atomicAdd(accp + 4*q + 2, v.z);
                                atomicAdd(accp + 4*q + 3, v.w);
                            }
                        }
                    }
                }
            }
        }

        // 16-lane butterfly reduce (stays within group: xor d<16)
#pragma unroll
        for (int d = 1; d < LPP; d <<= 1) {
            nbcnt += __shfl_xor_sync(FULL, nbcnt, d);
            cnt   += __shfl_xor_sync(FULL, cnt, d);
        }
        __syncwarp();                                    // group smem atomics visible

        // ---- MLP: lane owns outputs {2*ln, 2*ln+1} ----
        const float rinv = 1.f / (float)(cnt > 0 ? cnt : 1);
        const int ob = ln * 2;

        float h0 = sb1[ob], h1 = sb1[ob + 1];
#pragma unroll 8
        for (int k = 0; k < DIM; k++) {
            float c = s_ei[pt * PAD + k];
            float2 w = *(const float2*)(sW1 + k * DIM + ob);
            h0 = fmaf(c, w.x, h0); h1 = fmaf(c, w.y, h1);
        }
#pragma unroll 8
        for (int k = 0; k < DIM; k++) {
            float c = s_acc[pt * PAD + k] * rinv;
            float2 w = *(const float2*)(sW1 + (DIM + k) * DIM + ob);
            h0 = fmaf(c, w.x, h0); h1 = fmaf(c, w.y, h1);
        }
        h0 = fmaxf(h0, 0.f); h1 = fmaxf(h1, 0.f);
        s_h[pt * PAD + ob] = h0; s_h[pt * PAD + ob + 1] = h1;
        __syncwarp();                                    // group-private s_h

        float o0 = sb2[ob], o1 = sb2[ob + 1];
#pragma unroll 8
        for (int k = 0; k < DIM; k++) {
            float c = s_h[pt * PAD + k];
            float2 w = *(const float2*)(sW2 + k * DIM + ob);
            o0 = fmaf(c, w.x, o0); o1 = fmaf(c, w.y, o1);
        }

        bool cond = (__ldg(leaf + gi) > 0) && (nbcnt > 1) && (cnt > 0)
                 && (g_leafcnt[b] >= MINLEAF);

        float2 res = cond ? make_float2(o0, o1)
                          : make_float2(s_ei[pt * PAD + ob], s_ei[pt * PAD + ob + 1]);
        *(float2*)(out + (size_t)gi * DIM + ob) = res;   // coalesced

        __syncthreads();                                 // before next tile restage
    }
}

extern "C" void kernel_launch(void* const* d_in, const int* in_sizes, int n_in,
                              void* d_out, int out_size) {
    const float* points = (const float*)d_in[0];
    const float* emb    = (const float*)d_in[1];
    const int*   leaf   = (const int*)d_in[2];
    const float* W1     = (const float*)d_in[3];
    const float* b1     = (const float*)d_in[4];
    const float* W2     = (const float*)d_in[5];
    const float* b2     = (const float*)d_in[6];
    float* out = (float*)d_out;

    fused_kernel<<<NB, TPB>>>(points, emb, leaf, W1, b1, W2, b2, out);
}